// round 4
// baseline (speedup 1.0000x reference)
#include <cuda_runtime.h>
#include <math.h>

// Fixed shapes from setup_inputs
#define BSZ 32
#define TT  50
#define CC  80
#define AA  85          // 5 + C
#define HH  76
#define WW  76
#define HWX (HH*WW)     // 5776
#define SIGMA_F 8.0f

// Kernel B config
#define BBLK 128
#define BILP 2
#define BCHUNK (BBLK*BILP)                    // 256
#define BGX  ((HWX + BCHUNK - 1) / BCHUNK)    // 23
// Kernel C config
#define CWARPS 8
#define CBLK (CWARPS*32)

// ---------------- device scratch ----------------
__device__ int    g_neff[BSZ];
__device__ float  g_bx1[BSZ*TT], g_by1[BSZ*TT], g_bx2[BSZ*TT], g_by2[BSZ*TT], g_ba[BSZ*TT];
__device__ int    g_bcell[BSZ*TT];
__device__ float  g_btx[BSZ*TT], g_bty[BSZ*TT], g_btw[BSZ*TT], g_bth[BSZ*TT], g_bsc[BSZ*TT];
__device__ int    g_bcls[BSZ*TT];
__device__ double g_noobj[16];   // noobj partials from B (16 slots to spread atomics)
__device__ double g_acc[7];      // [0..3]=x,y,w,h  [4]=conf_obj  [5]=noobj_correction  [6]=cls
__device__ unsigned int g_doneC;

// ---------------- math helpers ----------------
// robust softplus = log(1+exp(v)); equals -clog(1-sigmoid(v)) and -clog(sigmoid(-v))
__device__ __forceinline__ float softplus_(float v) {
    return fmaxf(v, 0.0f) + __logf(1.0f + __expf(-fabsf(v)));
}
__device__ __forceinline__ float sigmoidf_(float v) {
    return __fdividef(1.0f, 1.0f + __expf(-v));
}
// bce(sigmoid(v), t) = t*softplus(-v) + (1-t)*softplus(v)
__device__ __forceinline__ float bce_logit_(float v, float t) {
    return t * softplus_(-v) + (1.0f - t) * softplus_(v);
}
__device__ __forceinline__ float sl1f_(float a, float b) {
    float d = fabsf(a - b);
    return (d < 1.0f) ? 0.5f * d * d : d - 0.5f;
}

// ---------------- Kernel A: parallel target prep (one block per batch) ----------------
__global__ __launch_bounds__(64) void yolo_prep(const float* __restrict__ targets) {
    __shared__ int s_val[TT], s_cellv[TT];
    __shared__ int s_pos;
    const int b = blockIdx.x;
    const int t = threadIdx.x;
    if (t == 0) s_pos = 0;

    float t0 = 0.f, t3 = 0.f, t4 = 0.f, gx = 0.f, gy = 0.f, gw = 0.f, gh = 0.f;
    int gi = 0, gj = 0, cell = 0;
    if (t < TT) {
        const float* tg = targets + ((size_t)b * TT + t) * 5;
        t0 = tg[0];
        float t1 = tg[1], t2 = tg[2];
        t3 = tg[3]; t4 = tg[4];
        bool valid = ((t0 + t1 + t2 + t3 + t4) != 0.0f);
        gx = t1 * (float)WW;
        gy = t2 * (float)HH;
        gw = t3 * (float)WW;
        gh = t4 * (float)HH;
        gi = min(max((int)gx, 0), WW - 1);
        gj = min(max((int)gy, 0), HH - 1);
        cell = gj * WW + gi;
        s_val[t]   = valid ? 1 : 0;
        s_cellv[t] = cell;
    }
    __syncthreads();
    if (t < TT && s_val[t]) {
        bool dup = false;
        for (int k = 0; k < t; k++)
            dup |= (s_val[k] && (s_cellv[k] == cell));
        if (!dup) {
            int p = atomicAdd(&s_pos, 1);
            int idx = b * TT + p;
            g_bx1[idx]  = fmaf(gw, -0.5f, gx);
            g_by1[idx]  = fmaf(gh, -0.5f, gy);
            g_bx2[idx]  = fmaf(gw,  0.5f, gx);
            g_by2[idx]  = fmaf(gh,  0.5f, gy);
            g_ba[idx]   = gw * gh;
            g_bcell[idx]= cell;
            g_btx[idx]  = gx - (float)gi;
            g_bty[idx]  = gy - (float)gj;
            g_btw[idx]  = logf(gw / SIGMA_F + 1e-16f);
            g_bth[idx]  = logf(gh / SIGMA_F + 1e-16f);
            g_bsc[idx]  = 2.0f - t3 * t4;
            g_bcls[idx] = min(max((int)t0, 0), CC - 1);
        }
    }
    __syncthreads();
    if (t == 0) g_neff[b] = s_pos;
}

// ---------------- Kernel B: uniform grid pass (ignore + noobj) ----------------
__global__ __launch_bounds__(BBLK) void yolo_noobj(const float* __restrict__ inp) {
    __shared__ float s_x1[TT], s_y1[TT], s_x2[TT], s_y2[TT], s_a[TT];
    __shared__ float s_red;
    const int b   = blockIdx.y;
    const int tid = threadIdx.x;

    const int ne = g_neff[b];
    if (tid == 0) s_red = 0.0f;
    if (tid < ne) {
        int idx = b * TT + tid;
        s_x1[tid] = g_bx1[idx];
        s_y1[tid] = g_by1[idx];
        s_x2[tid] = g_bx2[idx];
        s_y2[tid] = g_by2[idx];
        s_a[tid]  = g_ba[idx];
    }
    __syncthreads();

    const float* bbase = inp + (size_t)b * AA * HWX;
    const int c0 = blockIdx.x * BCHUNK + tid;

    bool  cval[BILP];
    float v4a[BILP], pae[BILP];
    float px1[BILP], px2[BILP], py1[BILP], py2[BILP];
    float m[BILP];

    #pragma unroll
    for (int u = 0; u < BILP; u++) {
        int c = c0 + u * BBLK;
        cval[u] = (c < HWX);
        int cc = cval[u] ? c : 0;
        float v0 = bbase[cc];
        float v1 = bbase[(size_t)1 * HWX + cc];
        float v2 = bbase[(size_t)2 * HWX + cc];
        float v3 = bbase[(size_t)3 * HWX + cc];
        v4a[u]   = bbase[(size_t)4 * HWX + cc];

        float xs = sigmoidf_(v0);
        float ys = sigmoidf_(v1);
        int i = cc % WW;
        int j = cc / WW;
        float px = xs + (float)i;
        float py = ys + (float)j;
        float pw = __expf(v2) * SIGMA_F;
        float ph = __expf(v3) * SIGMA_F;
        px1[u] = fmaf(pw, -0.5f, px); px2[u] = fmaf(pw, 0.5f, px);
        py1[u] = fmaf(ph, -0.5f, py); py2[u] = fmaf(ph, 0.5f, py);
        pae[u] = pw * ph + 1e-16f;
        m[u]   = -1e30f;
    }

    for (int e = 0; e < ne; e++) {
        float ex1 = s_x1[e], ey1 = s_y1[e];
        float ex2 = s_x2[e], ey2 = s_y2[e];
        float ea  = s_a[e];
        #pragma unroll
        for (int u = 0; u < BILP; u++) {
            float iw = fminf(ex2, px2[u]) - fmaxf(ex1, px1[u]);
            float ih = fminf(ey2, py2[u]) - fmaxf(ey1, py1[u]);
            iw = fmaxf(iw, 0.0f);
            ih = fmaxf(ih, 0.0f);
            float inter = iw * ih;
            m[u] = fmaxf(m[u], fmaf(inter, 3.0f, -ea));
        }
    }

    // noobj contribution: every NON-ignored cell (matched cells corrected in kernel C)
    float acc = 0.0f;
    #pragma unroll
    for (int u = 0; u < BILP; u++) {
        if (cval[u] && (m[u] < pae[u])) acc += softplus_(v4a[u]);
    }

    #pragma unroll
    for (int o = 16; o > 0; o >>= 1) acc += __shfl_down_sync(0xffffffffu, acc, o);
    if ((tid & 31) == 0 && acc != 0.0f) atomicAdd(&s_red, acc);
    __syncthreads();
    if (tid == 0 && s_red != 0.0f)
        atomicAdd(&g_noobj[(blockIdx.y * BGX + blockIdx.x) & 15], (double)s_red);
}

// ---------------- Kernel C: per-target obj losses (one warp per target) ----------------
__global__ __launch_bounds__(CBLK) void yolo_obj(const float* __restrict__ inp,
                                                 float* __restrict__ out) {
    __shared__ float s_x1[TT], s_y1[TT], s_x2[TT], s_y2[TT], s_a[TT];
    __shared__ float s_acc[7];
    const int b    = blockIdx.x;
    const int tid  = threadIdx.x;
    const int wid  = tid >> 5;
    const int lane = tid & 31;

    const int ne = g_neff[b];
    if (tid < 7) s_acc[tid] = 0.0f;
    if (tid < ne) {
        int idx = b * TT + tid;
        s_x1[tid] = g_bx1[idx];
        s_y1[tid] = g_by1[idx];
        s_x2[tid] = g_bx2[idx];
        s_y2[tid] = g_by2[idx];
        s_a[tid]  = g_ba[idx];
    }
    __syncthreads();

    const float* bbase = inp + (size_t)b * AA * HWX;

    for (int e = wid; e < ne; e += CWARPS) {
        const int idx  = b * TT + e;
        const int cell = g_bcell[idx];
        const float* base = bbase + cell;

        float v0 = base[0];
        float v1 = base[(size_t)1 * HWX];
        float v2 = base[(size_t)2 * HWX];
        float v3 = base[(size_t)3 * HWX];
        float v4 = base[(size_t)4 * HWX];

        // pred box (same expressions as kernel B -> bit-identical ignore decision)
        float xs = sigmoidf_(v0);
        float ys = sigmoidf_(v1);
        int i = cell % WW;
        int j = cell / WW;
        float px = xs + (float)i;
        float py = ys + (float)j;
        float pw = __expf(v2) * SIGMA_F;
        float ph = __expf(v3) * SIGMA_F;
        float px1 = fmaf(pw, -0.5f, px), px2 = fmaf(pw, 0.5f, px);
        float py1 = fmaf(ph, -0.5f, py), py2 = fmaf(ph, 0.5f, py);
        float pae = pw * ph + 1e-16f;

        // ignore test, lane-parallel over targets
        bool ig = false;
        for (int k = lane; k < ne; k += 32) {
            float iw = fminf(s_x2[k], px2) - fmaxf(s_x1[k], px1);
            float ih = fminf(s_y2[k], py2) - fmaxf(s_y1[k], py1);
            iw = fmaxf(iw, 0.0f);
            ih = fmaxf(ih, 0.0f);
            float inter = iw * ih;
            ig |= (fmaf(inter, 3.0f, -s_a[k]) >= pae);
        }
        ig = (__ballot_sync(0xffffffffu, ig) != 0u);

        // class BCE, lane-parallel over 80 classes
        const int cls = g_bcls[idx];
        float scl = 0.0f;
        for (int c = lane; c < CC; c += 32) {
            float vc = base[(size_t)(5 + c) * HWX];
            // bce(sigmoid(vc), onehot): cls -> softplus(-vc), else softplus(vc)
            scl += (c == cls) ? softplus_(-vc) : softplus_(vc);
        }
        #pragma unroll
        for (int o = 16; o > 0; o >>= 1) scl += __shfl_down_sync(0xffffffffu, scl, o);

        if (lane == 0) {
            float sc = g_bsc[idx];
            atomicAdd(&s_acc[0], sc * bce_logit_(v0, g_btx[idx]));
            atomicAdd(&s_acc[1], sc * bce_logit_(v1, g_bty[idx]));
            atomicAdd(&s_acc[2], sc * sl1f_(v2, g_btw[idx]));
            atomicAdd(&s_acc[3], sc * sl1f_(v3, g_bth[idx]));
            atomicAdd(&s_acc[4], softplus_(-v4));            // -clog(conf) at obj cell
            if (!ig) atomicAdd(&s_acc[5], softplus_(v4));    // noobj over-count correction
            atomicAdd(&s_acc[6], scl);
        }
    }
    __syncthreads();
    if (tid < 7 && s_acc[tid] != 0.0f) atomicAdd(&g_acc[tid], (double)s_acc[tid]);

    // ---- finalize in the last C block ----
    __shared__ bool s_last;
    if (tid == 0) {
        __threadfence();
        unsigned int ticket = atomicAdd(&g_doneC, 1u);
        s_last = (ticket == (unsigned int)(BSZ - 1));
    }
    __syncthreads();
    if (s_last && tid == 0) {
        __threadfence();
        volatile double* acc = g_acc;
        int nobj = 0;
        for (int k = 0; k < BSZ; k++) nobj += g_neff[k];
        double noobj_sum = 0.0;
        for (int k = 0; k < 16; k++) noobj_sum += g_noobj[k];
        double inv = 1.0 / (double)nobj;
        double lx = acc[0] * inv;
        double ly = acc[1] * inv;
        double lw = acc[2] * inv;
        double lh = acc[3] * inv;
        double lconf = (acc[4] + 0.5 * (noobj_sum - acc[5])) * inv;
        double lcls  = (nobj > 0) ? acc[6] * inv : 0.0;
        double loss = lx + ly + lw + lh + lconf + lcls;
        out[0] = (float)loss;
        out[1] = (float)lx;
        out[2] = (float)ly;
        out[3] = (float)lw;
        out[4] = (float)lh;
        out[5] = (float)lconf;
        out[6] = (float)lcls;
        // reset state for next graph replay
        for (int k = 0; k < 7;  k++) g_acc[k]   = 0.0;
        for (int k = 0; k < 16; k++) g_noobj[k] = 0.0;
        g_doneC = 0u;
    }
}

// ---------------- launch ----------------
extern "C" void kernel_launch(void* const* d_in, const int* in_sizes, int n_in,
                              void* d_out, int out_size) {
    const float* inp     = (const float*)d_in[0];   // [32, 85, 76, 76]
    const float* targets = (const float*)d_in[1];   // [32, 50, 5]
    float* out = (float*)d_out;

    yolo_prep<<<BSZ, 64>>>(targets);
    dim3 gridB(BGX, BSZ);
    yolo_noobj<<<gridB, BBLK>>>(inp);
    yolo_obj<<<BSZ, CBLK>>>(inp, out);
}

// round 5
// speedup vs baseline: 1.5172x; 1.5172x over previous
#include <cuda_runtime.h>
#include <math.h>

// Fixed shapes from setup_inputs
#define BSZ 32
#define TT  50
#define CC  80
#define AA  85          // 5 + C
#define HH  76
#define WW  76
#define HWX (HH*WW)     // 5776
#define SIGMA_F 8.0f

#define BLK   256
#define BILP  2
#define CHUNK (BLK*BILP)                   // 512
#define GXB   ((HWX + CHUNK - 1) / CHUNK)  // 12 grid-role x-slices
#define GXT   (GXB + 1)                    // +1 obj-role slice
#define NBLOCKS (GXT * BSZ)                // 416

// ---------------- device scratch ----------------
__device__ int    g_neff[BSZ];
__device__ double g_noobj[16];   // grid-role noobj partials (16 slots to spread atomics)
__device__ double g_acc[7];      // [0..3]=x,y,w,h [4]=conf_obj [5]=noobj_corr [6]=cls
__device__ unsigned int g_done;

// ---------------- math helpers ----------------
// robust softplus = log(1+exp(v)) = -clog(1-sigmoid(v)) = -clog(sigmoid(-v))
__device__ __forceinline__ float softplus_(float v) {
    return fmaxf(v, 0.0f) + __logf(1.0f + __expf(-fabsf(v)));
}
__device__ __forceinline__ float sigmoidf_(float v) {
    return __fdividef(1.0f, 1.0f + __expf(-v));
}
// bce(sigmoid(v), t) = t*softplus(-v) + (1-t)*softplus(v)
__device__ __forceinline__ float bce_logit_(float v, float t) {
    return t * softplus_(-v) + (1.0f - t) * softplus_(v);
}
__device__ __forceinline__ float sl1f_(float a, float b) {
    float d = fabsf(a - b);
    return (d < 1.0f) ? 0.5f * d * d : d - 0.5f;
}

// ---------------- single kernel, role-split blocks ----------------
__global__ __launch_bounds__(BLK) void yolo_one(const float* __restrict__ inp,
                                                const float* __restrict__ targets,
                                                float* __restrict__ out) {
    // compacted effective targets
    __shared__ float s_x1[TT], s_y1[TT], s_x2[TT], s_y2[TT], s_a[TT];
    __shared__ int   s_cell[TT];
    __shared__ float s_tx[TT], s_ty[TT], s_tw[TT], s_th[TT], s_sc[TT];
    __shared__ int   s_cls[TT];
    // prep temporaries
    __shared__ int   s_val[TT], s_vcell[TT];
    __shared__ int   s_ne;
    __shared__ float s_acc[7];

    const int bx  = blockIdx.x;   // 0..GXB-1 grid role, GXB obj role
    const int b   = blockIdx.y;
    const int tid = threadIdx.x;

    if (tid == 0) s_ne = 0;
    if (tid < 7)  s_acc[tid] = 0.0f;

    // ---- inline parallel prep (threads 0..TT-1) ----
    float gx = 0.f, gy = 0.f, gw = 0.f, gh = 0.f, t0 = 0.f, t3 = 0.f, t4 = 0.f;
    int gi = 0, gj = 0, mycell = 0;
    if (tid < TT) {
        const float* tg = targets + ((size_t)b * TT + tid) * 5;
        t0 = tg[0];
        float t1 = tg[1], t2 = tg[2];
        t3 = tg[3]; t4 = tg[4];
        bool valid = ((t0 + t1 + t2 + t3 + t4) != 0.0f);
        gx = t1 * (float)WW;
        gy = t2 * (float)HH;
        gw = t3 * (float)WW;
        gh = t4 * (float)HH;
        gi = min(max((int)gx, 0), WW - 1);
        gj = min(max((int)gy, 0), HH - 1);
        mycell = gj * WW + gi;
        s_val[tid]   = valid ? 1 : 0;
        s_vcell[tid] = mycell;
    }
    __syncthreads();
    if (tid < TT && s_val[tid]) {
        bool dup = false;
        for (int k = 0; k < tid; k++)
            dup |= (s_val[k] && (s_vcell[k] == mycell));
        if (!dup) {
            int p = atomicAdd(&s_ne, 1);
            s_x1[p]  = fmaf(gw, -0.5f, gx);
            s_y1[p]  = fmaf(gh, -0.5f, gy);
            s_x2[p]  = fmaf(gw,  0.5f, gx);
            s_y2[p]  = fmaf(gh,  0.5f, gy);
            s_a[p]   = gw * gh;
            s_cell[p]= mycell;
            s_tx[p]  = gx - (float)gi;
            s_ty[p]  = gy - (float)gj;
            s_tw[p]  = __logf(gw / SIGMA_F + 1e-16f);
            s_th[p]  = __logf(gh / SIGMA_F + 1e-16f);
            s_sc[p]  = 2.0f - t3 * t4;
            s_cls[p] = min(max((int)t0, 0), CC - 1);
        }
    }
    __syncthreads();
    const int ne = s_ne;
    const float* bbase = inp + (size_t)b * AA * HWX;

    if (bx < GXB) {
        // ================= grid role: uniform noobj + ignore =================
        const int c0 = bx * CHUNK + tid;

        bool  cval[BILP];
        float v4a[BILP], pae[BILP];
        float px1[BILP], px2[BILP], py1[BILP], py2[BILP], m[BILP];

        #pragma unroll
        for (int u = 0; u < BILP; u++) {
            int c = c0 + u * BLK;
            cval[u] = (c < HWX);
            int cc = cval[u] ? c : 0;
            float v0 = bbase[cc];
            float v1 = bbase[(size_t)1 * HWX + cc];
            float v2 = bbase[(size_t)2 * HWX + cc];
            float v3 = bbase[(size_t)3 * HWX + cc];
            v4a[u]   = bbase[(size_t)4 * HWX + cc];

            float xs = sigmoidf_(v0);
            float ys = sigmoidf_(v1);
            int i = cc % WW;
            int j = cc / WW;
            float px = xs + (float)i;
            float py = ys + (float)j;
            float pw = __expf(v2) * SIGMA_F;
            float ph = __expf(v3) * SIGMA_F;
            px1[u] = fmaf(pw, -0.5f, px); px2[u] = fmaf(pw, 0.5f, px);
            py1[u] = fmaf(ph, -0.5f, py); py2[u] = fmaf(ph, 0.5f, py);
            pae[u] = pw * ph + 1e-16f;
            m[u]   = -1e30f;
        }

        for (int e = 0; e < ne; e++) {
            float ex1 = s_x1[e], ey1 = s_y1[e];
            float ex2 = s_x2[e], ey2 = s_y2[e];
            float ea  = s_a[e];
            #pragma unroll
            for (int u = 0; u < BILP; u++) {
                float iw = fminf(ex2, px2[u]) - fmaxf(ex1, px1[u]);
                float ih = fminf(ey2, py2[u]) - fmaxf(ey1, py1[u]);
                iw = fmaxf(iw, 0.0f);
                ih = fmaxf(ih, 0.0f);
                float inter = iw * ih;
                // iou >= 0.5  <=>  3*inter - ga >= pa + 1e-16
                m[u] = fmaxf(m[u], fmaf(inter, 3.0f, -ea));
            }
        }

        float acc = 0.0f;
        #pragma unroll
        for (int u = 0; u < BILP; u++)
            if (cval[u] && (m[u] < pae[u])) acc += softplus_(v4a[u]);

        #pragma unroll
        for (int o = 16; o > 0; o >>= 1) acc += __shfl_down_sync(0xffffffffu, acc, o);
        if ((tid & 31) == 0 && acc != 0.0f) atomicAdd(&s_acc[0], acc);
        __syncthreads();
        if (tid == 0 && s_acc[0] != 0.0f)
            atomicAdd(&g_noobj[(b * GXB + bx) & 15], (double)s_acc[0]);
    } else {
        // ================= obj role: warp per target =================
        const int wid  = tid >> 5;
        const int lane = tid & 31;
        if (tid == 0) g_neff[b] = ne;

        for (int e = wid; e < ne; e += BLK / 32) {
            const int cell = s_cell[e];
            const float* base = bbase + cell;

            float v0 = base[0];
            float v1 = base[(size_t)1 * HWX];
            float v2 = base[(size_t)2 * HWX];
            float v3 = base[(size_t)3 * HWX];
            float v4 = base[(size_t)4 * HWX];

            // identical pred-box expressions as grid role -> identical ignore test
            float xs = sigmoidf_(v0);
            float ys = sigmoidf_(v1);
            int i = cell % WW;
            int j = cell / WW;
            float px = xs + (float)i;
            float py = ys + (float)j;
            float pw = __expf(v2) * SIGMA_F;
            float ph = __expf(v3) * SIGMA_F;
            float px1 = fmaf(pw, -0.5f, px), px2 = fmaf(pw, 0.5f, px);
            float py1 = fmaf(ph, -0.5f, py), py2 = fmaf(ph, 0.5f, py);
            float pae = pw * ph + 1e-16f;

            bool ig = false;
            for (int k = lane; k < ne; k += 32) {
                float iw = fminf(s_x2[k], px2) - fmaxf(s_x1[k], px1);
                float ih = fminf(s_y2[k], py2) - fmaxf(s_y1[k], py1);
                iw = fmaxf(iw, 0.0f);
                ih = fmaxf(ih, 0.0f);
                float inter = iw * ih;
                ig |= (fmaf(inter, 3.0f, -s_a[k]) >= pae);
            }
            ig = (__ballot_sync(0xffffffffu, ig) != 0u);

            // class BCE lane-parallel over 80 classes (scattered loads, MLP=32)
            const int cls = s_cls[e];
            float scl = 0.0f;
            for (int c = lane; c < CC; c += 32) {
                float vc = base[(size_t)(5 + c) * HWX];
                scl += (c == cls) ? softplus_(-vc) : softplus_(vc);
            }
            #pragma unroll
            for (int o = 16; o > 0; o >>= 1) scl += __shfl_down_sync(0xffffffffu, scl, o);

            if (lane == 0) {
                float sc = s_sc[e];
                atomicAdd(&s_acc[0], sc * bce_logit_(v0, s_tx[e]));
                atomicAdd(&s_acc[1], sc * bce_logit_(v1, s_ty[e]));
                atomicAdd(&s_acc[2], sc * sl1f_(v2, s_tw[e]));
                atomicAdd(&s_acc[3], sc * sl1f_(v3, s_th[e]));
                atomicAdd(&s_acc[4], softplus_(-v4));          // -clog(conf) at obj cell
                if (!ig) atomicAdd(&s_acc[5], softplus_(v4));  // noobj over-count correction
                atomicAdd(&s_acc[6], scl);
            }
        }
        __syncthreads();
        if (tid < 7 && s_acc[tid] != 0.0f) atomicAdd(&g_acc[tid], (double)s_acc[tid]);
    }

    // ---- finalize in the last-arriving block ----
    __shared__ bool s_last;
    if (tid == 0) {
        __threadfence();
        unsigned int ticket = atomicAdd(&g_done, 1u);
        s_last = (ticket == (unsigned int)(NBLOCKS - 1));
    }
    __syncthreads();
    if (s_last && tid == 0) {
        __threadfence();
        volatile double* acc = g_acc;
        int nobj = 0;
        for (int k = 0; k < BSZ; k++) nobj += g_neff[k];
        double noobj_sum = 0.0;
        for (int k = 0; k < 16; k++) noobj_sum += g_noobj[k];
        double inv = 1.0 / (double)nobj;
        double lx = acc[0] * inv;
        double ly = acc[1] * inv;
        double lw = acc[2] * inv;
        double lh = acc[3] * inv;
        double lconf = (acc[4] + 0.5 * (noobj_sum - acc[5])) * inv;
        double lcls  = (nobj > 0) ? acc[6] * inv : 0.0;  // sum(tcls) == n_obj
        double loss = lx + ly + lw + lh + lconf + lcls;
        out[0] = (float)loss;
        out[1] = (float)lx;
        out[2] = (float)ly;
        out[3] = (float)lw;
        out[4] = (float)lh;
        out[5] = (float)lconf;
        out[6] = (float)lcls;
        // reset for next graph replay
        for (int k = 0; k < 7;  k++) g_acc[k]   = 0.0;
        for (int k = 0; k < 16; k++) g_noobj[k] = 0.0;
        g_done = 0u;
    }
}

// ---------------- launch ----------------
extern "C" void kernel_launch(void* const* d_in, const int* in_sizes, int n_in,
                              void* d_out, int out_size) {
    const float* inp     = (const float*)d_in[0];   // [32, 85, 76, 76]
    const float* targets = (const float*)d_in[1];   // [32, 50, 5]
    float* out = (float*)d_out;

    dim3 grid(GXT, BSZ);
    yolo_one<<<grid, BLK>>>(inp, targets, out);
}